// round 11
// baseline (speedup 1.0000x reference)
#include <cuda_runtime.h>
#include <cuda_fp16.h>
#include <cstdint>
#include <cstddef>

// ---------------- problem constants ----------------
#define T     4
#define WQ    75
#define WAY   5
#define SHOT  5
#define WS    (WAY*SHOT)        // 25
#define C     640
#define HW    100
#define MS    512               // padded rows per way (500 real + 12 zero)
#define MTOT  (WAY*MS)          // 2560
#define NQ    (WQ*HW)           // 7500
#define NPAD  7552              // 59 * 128 -> grid 4720 = 15*296 + 280 (good tail)
#define BM    128
#define BN    128
#define BKH   64                // K halves per chunk => 128B smem rows
#define KT    (C/BKH)           // 10
#define STAGES 3

#define A_BYTES    (BM*128)     // 16384
#define B_BYTES    (BN*128)     // 16384
#define STAGE_BYTES (A_BYTES + B_BYTES)              // 32768
#define SMEM_TOTAL  (STAGES*STAGE_BYTES)             // 98304

#define SWZ(o) ((o) ^ (((o) >> 3) & 0x70))
#define WAITG(n) asm volatile("cp.async.wait_group %0;" :: "n"(n))

__device__ __forceinline__ uint32_t smem_u32(const void* p) {
    uint32_t a;
    asm("{ .reg .u64 t; cvta.to.shared.u64 t, %1; cvt.u32.u64 %0, t; }" : "=r"(a) : "l"(p));
    return a;
}

// ---------------- scratch (__device__ globals) ----------------
__device__ __align__(256) __half g_S16[(size_t)T * MTOT * C];   // 13.1 MB
__device__ __align__(256) __half g_Q16[(size_t)T * NPAD * C];   // 38.7 MB
__device__ float g_meanS[T * WAY * C];
__device__ __align__(16) float g_colsum[T * WAY * NPAD];

// ---------------- kernel 1: support channel means (all t) ----------------
__global__ void means_s_kernel(const float* __restrict__ sf, float* __restrict__ ms) {
    int wid  = (blockIdx.x * blockDim.x + threadIdx.x) >> 5;
    int lane = threadIdx.x & 31;
    if (wid >= T * WAY * C) return;
    int c   = wid % C;
    int way = (wid / C) % WAY;
    int t   = wid / (C * WAY);
    float v = 0.f;
    #pragma unroll
    for (int sh = 0; sh < SHOT; sh++) {
        const float* p = sf + ((size_t)((t * WAY + way) * SHOT + sh) * C + c) * HW;
        v += p[lane] + p[lane + 32] + p[lane + 64];
        if (lane < 4) v += p[lane + 96];
    }
    #pragma unroll
    for (int o = 16; o; o >>= 1) v += __shfl_xor_sync(~0u, v, o);
    if (!lane) ms[wid] = v * (1.0f / (SHOT * HW));
}

// ---------------- kernel 2: per-t merged prep (center_s + center_q + pads + zero colsum) ----
// block ranges within one t:
//   [0,250)      center_s   (25 ws x 10 c-chunks)
//   [250,1000)   center_q   (75 q  x 10 c-chunks)
//   [1000,1075)  S padding  (19200 half2)
//   [1075,1140)  Q padding  (16640 half2)
//   [1140,1177)  colsum zero (9440 float4)
#define MERGED_T_BLOCKS 1177
__global__ void __launch_bounds__(256) merged_prep_kernel(
        const float* __restrict__ sf, const float* __restrict__ qf,
        const float* __restrict__ ms,
        __half* __restrict__ S, __half* __restrict__ Q, float* __restrict__ cs,
        int t) {
    __shared__ float tile[64 * 101];
    __shared__ float mean[64];
    int b = blockIdx.x;
    int tid = threadIdx.x;

    if (b < 250) {
        // ---- center+transpose support ----
        int cc = b % 10;
        int ws = b / 10;
        int way = ws / SHOT, sh = ws % SHOT;
        int c0 = cc * 64;
        const float* src = sf + ((size_t)(t * WS + ws) * C + c0) * HW;
        #pragma unroll
        for (int i = 0; i < 25; i++) {
            int idx = tid + i * 256;
            tile[(idx / 100) * 101 + (idx % 100)] = src[idx];
        }
        __syncthreads();
        const float* mrow = ms + (t * WAY + way) * C + c0;
        __half2* dst = (__half2*)(S + ((size_t)t * MTOT + way * MS + sh * HW) * C + c0);
        for (int i = tid; i < 32 * HW; i += 256) {
            int n = i / 32, cp = i % 32;
            float v0 = tile[(cp * 2) * 101 + n] - mrow[cp * 2];
            float v1 = tile[(cp * 2 + 1) * 101 + n] - mrow[cp * 2 + 1];
            dst[(size_t)n * (C / 2) + cp] = __floats2half2_rn(v0, v1);
        }
    } else if (b < 1000) {
        // ---- center(fused mean)+transpose query ----
        int bb = b - 250;
        int cc = bb % 10;
        int q  = bb / 10;
        int c0 = cc * 64;
        const float* src = qf + ((size_t)(t * WQ + q) * C + c0) * HW;
        int warp = tid >> 5, lane = tid & 31;
        #pragma unroll
        for (int i = 0; i < 25; i++) {
            int idx = tid + i * 256;
            tile[(idx / 100) * 101 + (idx % 100)] = src[idx];
        }
        __syncthreads();
        #pragma unroll
        for (int r = warp; r < 64; r += 8) {
            const float* row = &tile[r * 101];
            float v = row[lane] + row[lane + 32] + row[lane + 64];
            if (lane < 4) v += row[lane + 96];
            #pragma unroll
            for (int o = 16; o; o >>= 1) v += __shfl_xor_sync(~0u, v, o);
            if (!lane) mean[r] = v * (1.0f / HW);
        }
        __syncthreads();
        __half2* dst = (__half2*)(Q + ((size_t)t * NPAD + q * HW) * C + c0);
        for (int i = tid; i < 32 * HW; i += 256) {
            int n = i / 32, cp = i % 32;
            float v0 = tile[(cp * 2) * 101 + n] - mean[cp * 2];
            float v1 = tile[(cp * 2 + 1) * 101 + n] - mean[cp * 2 + 1];
            dst[(size_t)n * (C / 2) + cp] = __floats2half2_rn(v0, v1);
        }
    } else if (b < 1075) {
        // ---- zero S padding rows (rows 500..511 of each way) ----
        int i = (b - 1000) * 256 + tid;            // < 19200
        int cp = i % (C / 2);
        int r  = (i / (C / 2)) % (MS - SHOT * HW);
        int wy = i / ((C / 2) * (MS - SHOT * HW));
        ((__half2*)S)[((size_t)t * MTOT + wy * MS + SHOT * HW + r) * (C / 2) + cp] =
            __floats2half2_rn(0.f, 0.f);
    } else if (b < 1140) {
        // ---- zero Q padding rows (rows 7500..7551) ----
        int i = (b - 1075) * 256 + tid;            // < 16640
        int cp = i % (C / 2);
        int r  = i / (C / 2);
        ((__half2*)Q)[((size_t)t * NPAD + NQ + r) * (C / 2) + cp] =
            __floats2half2_rn(0.f, 0.f);
    } else {
        // ---- zero colsum for this t (WAY*NPAD floats = 9440 float4) ----
        int i = (b - 1140) * 256 + tid;
        if (i < WAY * NPAD / 4)
            ((float4*)cs)[(size_t)t * (WAY * NPAD / 4) + i] =
                make_float4(0.f, 0.f, 0.f, 0.f);
    }
}

// ---------------- kernel 3: fp16 HMMA GEMM (128x128) + fused column sum-of-squares ----------------
// R7 config: 128 threads (4 warps 2x2), warp tile 64x64, 2 CTAs/SM, 3 stages. Per-t launch.
__global__ void __launch_bounds__(128, 2) gemm_hmma_kernel(const __half* __restrict__ A,
                                                           const __half* __restrict__ B,
                                                           float* __restrict__ colsum,
                                                           int t) {
    extern __shared__ char smem[];
    const uint32_t sb = smem_u32(smem);

    const int tid  = threadIdx.x;
    const int warp = tid >> 5, lane = tid & 31;
    const int wm = warp & 1;          // 0..1 : 64-row half (M)
    const int wn = warp >> 1;         // 0..1 : 64-col half (N)
    const int gid = lane >> 2, tig = lane & 3;

    const int m0 = blockIdx.y * BM;
    const int n0 = blockIdx.x * BN;
    const __half* Ap = A + ((size_t)t * MTOT + m0) * C;
    const __half* Bp = B + ((size_t)t * NPAD + n0) * C;

    const int arow = lane & 15;
    const int akof = (lane >> 4) * 16;
    const int brow = ((lane >> 4) << 3) | (lane & 7);
    const int bkof = ((lane >> 3) & 1) * 16;

    auto issue = [&](int kc) {
        const int s  = kc % STAGES;
        const int k0 = kc * BKH;
        const uint32_t sA = sb + s * STAGE_BYTES;
        const uint32_t sB = sA + A_BYTES;
        #pragma unroll
        for (int it = 0; it < 8; it++) {               // A: 1024 x 16B
            int i   = tid + it * 128;
            int row = i >> 3, ch = i & 7;
            uint32_t dst = sA + SWZ(row * 128 + ch * 16);
            const __half* src = Ap + (size_t)row * C + k0 + ch * 8;
            asm volatile("cp.async.cg.shared.global [%0], [%1], 16;" :: "r"(dst), "l"(src));
        }
        #pragma unroll
        for (int it = 0; it < 8; it++) {               // B: 1024 x 16B
            int i   = tid + it * 128;
            int row = i >> 3, ch = i & 7;
            uint32_t dst = sB + SWZ(row * 128 + ch * 16);
            const __half* src = Bp + (size_t)row * C + k0 + ch * 8;
            asm volatile("cp.async.cg.shared.global [%0], [%1], 16;" :: "r"(dst), "l"(src));
        }
        asm volatile("cp.async.commit_group;");
    };

    float acc[4][8][4];
    #pragma unroll
    for (int mi = 0; mi < 4; mi++)
        #pragma unroll
        for (int ni = 0; ni < 8; ni++)
            #pragma unroll
            for (int r = 0; r < 4; r++) acc[mi][ni][r] = 0.f;

    issue(0); issue(1);

    for (int kc = 0; kc < KT; kc++) {
        if (kc < KT - 1) { WAITG(1); }   // stage kc complete (1 newer group may pend)
        else             { WAITG(0); }
        __syncthreads();                 // data visible + all warps done reading stage (kc-1)%3
        if (kc + 2 < KT) issue(kc + 2);  // writes stage (kc-1)%3 — safe after the sync

        const uint32_t sA = sb + (kc % STAGES) * STAGE_BYTES;
        const uint32_t sB = sA + A_BYTES;

        #pragma unroll
        for (int ks = 0; ks < 4; ks++) {
            const int kb = ks * 32;
            uint32_t a[4][4], b[8][2];
            #pragma unroll
            for (int mi = 0; mi < 4; mi++) {
                uint32_t addr = sA + SWZ((wm * 64 + mi * 16 + arow) * 128 + kb + akof);
                asm volatile("ldmatrix.sync.aligned.m8n8.x4.shared.b16 {%0,%1,%2,%3}, [%4];"
                             : "=r"(a[mi][0]), "=r"(a[mi][1]), "=r"(a[mi][2]), "=r"(a[mi][3])
                             : "r"(addr));
            }
            #pragma unroll
            for (int nj = 0; nj < 4; nj++) {
                uint32_t addr = sB + SWZ((wn * 64 + nj * 16 + brow) * 128 + kb + bkof);
                asm volatile("ldmatrix.sync.aligned.m8n8.x4.shared.b16 {%0,%1,%2,%3}, [%4];"
                             : "=r"(b[nj*2][0]), "=r"(b[nj*2][1]),
                               "=r"(b[nj*2+1][0]), "=r"(b[nj*2+1][1])
                             : "r"(addr));
            }
            #pragma unroll
            for (int mi = 0; mi < 4; mi++)
                #pragma unroll
                for (int ni = 0; ni < 8; ni++) {
                    asm volatile(
                        "mma.sync.aligned.m16n8k16.row.col.f32.f16.f16.f32 "
                        "{%0,%1,%2,%3}, {%4,%5,%6,%7}, {%8,%9}, {%0,%1,%2,%3};"
                        : "+f"(acc[mi][ni][0]), "+f"(acc[mi][ni][1]),
                          "+f"(acc[mi][ni][2]), "+f"(acc[mi][ni][3])
                        : "r"(a[mi][0]), "r"(a[mi][1]), "r"(a[mi][2]), "r"(a[mi][3]),
                          "r"(b[ni][0]), "r"(b[ni][1]));
                }
        }
    }

    // -------- fused epilogue: column sum of squares over this CTA's 128 rows --------
    const int way = m0 / MS;
    float* cs = colsum + ((size_t)t * WAY + way) * NPAD + n0;
    #pragma unroll
    for (int ni = 0; ni < 8; ni++) {
        float v0 = 0.f, v1 = 0.f;
        #pragma unroll
        for (int mi = 0; mi < 4; mi++) {
            v0 += acc[mi][ni][0] * acc[mi][ni][0] + acc[mi][ni][2] * acc[mi][ni][2];
            v1 += acc[mi][ni][1] * acc[mi][ni][1] + acc[mi][ni][3] * acc[mi][ni][3];
        }
        #pragma unroll
        for (int o = 4; o < 32; o <<= 1) {
            v0 += __shfl_xor_sync(~0u, v0, o);
            v1 += __shfl_xor_sync(~0u, v1, o);
        }
        if (gid == 0) {
            int col = wn * 64 + ni * 8 + tig * 2;
            atomicAdd(&cs[col], v0);
            atomicAdd(&cs[col + 1], v1);
        }
    }
}

// ---------------- kernel 4: /99, LeakyReLU(0.2), conv1d(k=stride=100), +bias ----------------
__global__ void final_kernel(const float* __restrict__ colsum, const float* __restrict__ cw,
                             const float* __restrict__ cb, float* __restrict__ out) {
    int wid  = (blockIdx.x * blockDim.x + threadIdx.x) >> 5;
    int lane = threadIdx.x & 31;
    if (wid >= T * WQ * WAY) return;
    int w = wid % WAY;
    int q = (wid / WAY) % WQ;
    int t = wid / (WAY * WQ);
    const float* cs = colsum + ((size_t)t * WAY + w) * NPAD + q * HW;
    float v = 0.f;
    #pragma unroll
    for (int i = 0; i < 4; i++) {
        int n = lane + 32 * i;
        if (n < HW) {
            float x = cs[n] * (1.0f / 99.0f);
            x = (x >= 0.f) ? x : 0.2f * x;
            v += x * cw[n];
        }
    }
    #pragma unroll
    for (int o = 16; o; o >>= 1) v += __shfl_xor_sync(~0u, v, o);
    if (!lane) out[wid] = v + cb[0];
}

// ---------------- launch: fork-join two-stream schedule (graph-capturable) ----------------
extern "C" void kernel_launch(void* const* d_in, const int* in_sizes, int n_in,
                              void* d_out, int out_size) {
    const float* qf = (const float*)d_in[0];
    const float* sf = (const float*)d_in[1];
    const float* cw = (const float*)d_in[2];
    const float* cb = (const float*)d_in[3];
    float* out = (float*)d_out;

    __half *dS, *dQ;
    float *dMS, *dCS;
    cudaGetSymbolAddress((void**)&dS,  g_S16);
    cudaGetSymbolAddress((void**)&dQ,  g_Q16);
    cudaGetSymbolAddress((void**)&dMS, g_meanS);
    cudaGetSymbolAddress((void**)&dCS, g_colsum);

    cudaFuncSetAttribute(gemm_hmma_kernel, cudaFuncAttributeMaxDynamicSharedMemorySize, SMEM_TOTAL);

    // side stream + events (created/destroyed per call; replays use the captured graph,
    // so host API cost never appears in timing; net device-mem delta is 0)
    cudaStream_t s2;
    cudaStreamCreateWithFlags(&s2, cudaStreamNonBlocking);
    cudaEvent_t evPrep[T], evG;
    for (int t = 0; t < T; t++) cudaEventCreateWithFlags(&evPrep[t], cudaEventDisableTiming);
    cudaEventCreateWithFlags(&evG, cudaEventDisableTiming);

    // 1) support means (stream 0; prerequisite for S centering)
    {
        int warps = T * WAY * C;
        means_s_kernel<<<(warps * 32 + 255) / 256, 256>>>(sf, dMS);
    }
    // 2) per-t: prep on stream 0, GEMM on s2 gated by an event (overlaps prep of later t)
    dim3 ggrid(NPAD / BN, MTOT / BM, 1);   // (59, 20)
    for (int t = 0; t < T; t++) {
        merged_prep_kernel<<<MERGED_T_BLOCKS, 256>>>(sf, qf, dMS, dS, dQ, dCS, t);
        cudaEventRecord(evPrep[t], 0);
        cudaStreamWaitEvent(s2, evPrep[t], 0);
        gemm_hmma_kernel<<<ggrid, 128, SMEM_TOTAL, s2>>>(dS, dQ, dCS, t);
    }
    // 3) join GEMM stream back, then final score on stream 0
    cudaEventRecord(evG, s2);
    cudaStreamWaitEvent(0, evG, 0);
    {
        int warps = T * WQ * WAY;
        final_kernel<<<(warps * 32 + 255) / 256, 256>>>(dCS, cw, cb, out);
    }

    for (int t = 0; t < T; t++) cudaEventDestroy(evPrep[t]);
    cudaEventDestroy(evG);
    cudaStreamDestroy(s2);
}

// round 13
// speedup vs baseline: 1.0819x; 1.0819x over previous
#include <cuda_runtime.h>
#include <cuda_fp16.h>
#include <cstdint>
#include <cstddef>

// ---------------- problem constants ----------------
#define T     4
#define WQ    75
#define WAY   5
#define SHOT  5
#define WS    (WAY*SHOT)        // 25
#define C     640
#define HW    100
#define MS    512               // padded rows per way (500 real + 12 zero)
#define MTOT  (WAY*MS)          // 2560
#define NQ    (WQ*HW)           // 7500
#define NPAD  7552              // 59 * 128 -> grid 4720 = 15*296 + 280 (good tail)
#define BM    128
#define BN    128
#define BKH   64                // K halves per chunk => 128B smem rows
#define KT    (C/BKH)           // 10
#define STAGES 3

#define A_BYTES    (BM*128)     // 16384
#define B_BYTES    (BN*128)     // 16384
#define STAGE_BYTES (A_BYTES + B_BYTES)              // 32768
#define SMEM_TOTAL  (STAGES*STAGE_BYTES)             // 98304

#define SWZ(o) ((o) ^ (((o) >> 3) & 0x70))
#define WAITG(n) asm volatile("cp.async.wait_group %0;" :: "n"(n))

__device__ __forceinline__ uint32_t smem_u32(const void* p) {
    uint32_t a;
    asm("{ .reg .u64 t; cvta.to.shared.u64 t, %1; cvt.u32.u64 %0, t; }" : "=r"(a) : "l"(p));
    return a;
}

__device__ __forceinline__ uint32_t h2_as_u32(__half2 h) {
    union { __half2 h; uint32_t u; } cvt;
    cvt.h = h;
    return cvt.u;
}

// ---------------- scratch (__device__ globals) ----------------
__device__ __align__(256) __half g_S16[(size_t)T * MTOT * C];   // 13.1 MB
__device__ __align__(256) __half g_Q16[(size_t)T * NPAD * C];   // 38.7 MB
__device__ float g_meanS[T * WAY * C];
__device__ __align__(16) float g_colsum[T * WAY * NPAD];

// ---------------- kernel 1: support channel means ----------------
__global__ void means_s_kernel(const float* __restrict__ sf, float* __restrict__ ms) {
    int wid  = (blockIdx.x * blockDim.x + threadIdx.x) >> 5;
    int lane = threadIdx.x & 31;
    if (wid >= T * WAY * C) return;
    int c   = wid % C;
    int way = (wid / C) % WAY;
    int t   = wid / (C * WAY);
    float v = 0.f;
    #pragma unroll
    for (int sh = 0; sh < SHOT; sh++) {
        const float* p = sf + ((size_t)((t * WAY + way) * SHOT + sh) * C + c) * HW;
        v += p[lane] + p[lane + 32] + p[lane + 64];
        if (lane < 4) v += p[lane + 96];
    }
    #pragma unroll
    for (int o = 16; o; o >>= 1) v += __shfl_xor_sync(~0u, v, o);
    if (!lane) ms[wid] = v * (1.0f / (SHOT * HW));
}

// ---------------- kernel 2: MERGED center_s + center_q + pads + zero (vectorized) ----
#define CS_BLOCKS  (T * WS * (C/64))     // 1000
#define CQ_BLOCKS  (T * WQ * (C/64))     // 3000
#define NS_PAD     (T * WAY * (MS - SHOT*HW) * (C/2))   // 76800 half2
#define NQ_PAD     (T * (NPAD - NQ) * (C/2))            // 66560 half2
#define NSP_BLOCKS (NS_PAD / 256)        // 300
#define NQP_BLOCKS (NQ_PAD / 256)        // 260
#define CSZ_ELEMS  (T * WAY * NPAD / 4)  // 37760 float4
#define CSZ_BLOCKS ((CSZ_ELEMS + 255) / 256)  // 148
#define MERGED_BLOCKS (CS_BLOCKS + CQ_BLOCKS + NSP_BLOCKS + NQP_BLOCKS + CSZ_BLOCKS)

// load a 64x100 f32 tile with float4 LDG (1600 LDG.128 instead of 6400 LDG.32)
__device__ __forceinline__ void load_tile_f4(const float* __restrict__ src,
                                             float* __restrict__ tile, int tid) {
    #pragma unroll
    for (int i = 0; i < 7; i++) {
        int idx4 = tid + i * 256;
        if (idx4 < 1600) {                 // 64 rows * 25 float4
            float4 v = reinterpret_cast<const float4*>(src)[idx4];
            int row = idx4 / 25, col = (idx4 % 25) * 4;
            float* tr = &tile[row * 101 + col];
            tr[0] = v.x; tr[1] = v.y; tr[2] = v.z; tr[3] = v.w;
        }
    }
}

__global__ void __launch_bounds__(256) merged_prep_kernel(
        const float* __restrict__ sf, const float* __restrict__ qf,
        const float* __restrict__ ms,
        __half* __restrict__ S, __half* __restrict__ Q, float* __restrict__ cs) {
    __shared__ float tile[64 * 101];
    __shared__ float mean[64];
    int b = blockIdx.x;
    int tid = threadIdx.x;

    if (b < CS_BLOCKS) {
        // ---- center+transpose support ----
        int cc = b % (C / 64);
        int ws = (b / (C / 64)) % WS;
        int t  = b / ((C / 64) * WS);
        int way = ws / SHOT, sh = ws % SHOT;
        int c0 = cc * 64;
        const float* src = sf + ((size_t)(t * WS + ws) * C + c0) * HW;
        load_tile_f4(src, tile, tid);
        __syncthreads();
        const float* mrow = ms + (t * WAY + way) * C + c0;
        uint2* dst = (uint2*)(S + ((size_t)t * MTOT + way * MS + sh * HW) * C + c0);
        // 16 uint2 per spatial row n (64 ch); i over 16*HW
        for (int i = tid; i < 16 * HW; i += 256) {
            int n = i / 16, cpp = i % 16;
            int c = cpp * 4;
            float v0 = tile[(c    ) * 101 + n] - mrow[c    ];
            float v1 = tile[(c + 1) * 101 + n] - mrow[c + 1];
            float v2 = tile[(c + 2) * 101 + n] - mrow[c + 2];
            float v3 = tile[(c + 3) * 101 + n] - mrow[c + 3];
            uint2 o;
            o.x = h2_as_u32(__floats2half2_rn(v0, v1));
            o.y = h2_as_u32(__floats2half2_rn(v2, v3));
            dst[(size_t)n * (C / 4) + cpp] = o;
        }
    } else if (b < CS_BLOCKS + CQ_BLOCKS) {
        // ---- center(fused mean)+transpose query ----
        int bb = b - CS_BLOCKS;
        int cc = bb % (C / 64);
        int q  = (bb / (C / 64)) % WQ;
        int t  = bb / ((C / 64) * WQ);
        int c0 = cc * 64;
        const float* src = qf + ((size_t)(t * WQ + q) * C + c0) * HW;
        int warp = tid >> 5, lane = tid & 31;
        load_tile_f4(src, tile, tid);
        __syncthreads();
        #pragma unroll
        for (int r = warp; r < 64; r += 8) {
            const float* row = &tile[r * 101];
            float v = row[lane] + row[lane + 32] + row[lane + 64];
            if (lane < 4) v += row[lane + 96];
            #pragma unroll
            for (int o = 16; o; o >>= 1) v += __shfl_xor_sync(~0u, v, o);
            if (!lane) mean[r] = v * (1.0f / HW);
        }
        __syncthreads();
        uint2* dst = (uint2*)(Q + ((size_t)t * NPAD + q * HW) * C + c0);
        for (int i = tid; i < 16 * HW; i += 256) {
            int n = i / 16, cpp = i % 16;
            int c = cpp * 4;
            float v0 = tile[(c    ) * 101 + n] - mean[c    ];
            float v1 = tile[(c + 1) * 101 + n] - mean[c + 1];
            float v2 = tile[(c + 2) * 101 + n] - mean[c + 2];
            float v3 = tile[(c + 3) * 101 + n] - mean[c + 3];
            uint2 o;
            o.x = h2_as_u32(__floats2half2_rn(v0, v1));
            o.y = h2_as_u32(__floats2half2_rn(v2, v3));
            dst[(size_t)n * (C / 4) + cpp] = o;
        }
    } else if (b < CS_BLOCKS + CQ_BLOCKS + NSP_BLOCKS) {
        // ---- zero S padding rows ----
        int i = (b - CS_BLOCKS - CQ_BLOCKS) * 256 + tid;
        int cp = i % (C / 2);
        int r  = (i / (C / 2)) % (MS - SHOT * HW);
        int wy = (i / ((C / 2) * (MS - SHOT * HW))) % WAY;
        int t  = i / ((C / 2) * (MS - SHOT * HW) * WAY);
        ((__half2*)S)[((size_t)t * MTOT + wy * MS + SHOT * HW + r) * (C / 2) + cp] =
            __floats2half2_rn(0.f, 0.f);
    } else if (b < CS_BLOCKS + CQ_BLOCKS + NSP_BLOCKS + NQP_BLOCKS) {
        // ---- zero Q padding rows ----
        int i = (b - CS_BLOCKS - CQ_BLOCKS - NSP_BLOCKS) * 256 + tid;
        int cp = i % (C / 2);
        int r  = (i / (C / 2)) % (NPAD - NQ);
        int t  = i / ((C / 2) * (NPAD - NQ));
        ((__half2*)Q)[((size_t)t * NPAD + NQ + r) * (C / 2) + cp] =
            __floats2half2_rn(0.f, 0.f);
    } else {
        // ---- zero colsum ----
        int i = (b - CS_BLOCKS - CQ_BLOCKS - NSP_BLOCKS - NQP_BLOCKS) * 256 + tid;
        if (i < CSZ_ELEMS)
            ((float4*)cs)[i] = make_float4(0.f, 0.f, 0.f, 0.f);
    }
}

// ---------------- kernel 3: fp16 HMMA GEMM (128x128) + fused column sum-of-squares ----------------
// R7 config: 128 threads (4 warps 2x2), warp tile 64x64, 2 CTAs/SM, 3 stages.
__global__ void __launch_bounds__(128, 2) gemm_hmma_kernel(const __half* __restrict__ A,
                                                           const __half* __restrict__ B,
                                                           float* __restrict__ colsum) {
    extern __shared__ char smem[];
    const uint32_t sb = smem_u32(smem);

    const int tid  = threadIdx.x;
    const int warp = tid >> 5, lane = tid & 31;
    const int wm = warp & 1;          // 0..1 : 64-row half (M)
    const int wn = warp >> 1;         // 0..1 : 64-col half (N)
    const int gid = lane >> 2, tig = lane & 3;

    const int t  = blockIdx.z;
    const int m0 = blockIdx.y * BM;
    const int n0 = blockIdx.x * BN;
    const __half* Ap = A + ((size_t)t * MTOT + m0) * C;
    const __half* Bp = B + ((size_t)t * NPAD + n0) * C;

    const int arow = lane & 15;
    const int akof = (lane >> 4) * 16;
    const int brow = ((lane >> 4) << 3) | (lane & 7);
    const int bkof = ((lane >> 3) & 1) * 16;

    auto issue = [&](int kc) {
        const int s  = kc % STAGES;
        const int k0 = kc * BKH;
        const uint32_t sA = sb + s * STAGE_BYTES;
        const uint32_t sB = sA + A_BYTES;
        #pragma unroll
        for (int it = 0; it < 8; it++) {               // A: 1024 x 16B
            int i   = tid + it * 128;
            int row = i >> 3, ch = i & 7;
            uint32_t dst = sA + SWZ(row * 128 + ch * 16);
            const __half* src = Ap + (size_t)row * C + k0 + ch * 8;
            asm volatile("cp.async.cg.shared.global [%0], [%1], 16;" :: "r"(dst), "l"(src));
        }
        #pragma unroll
        for (int it = 0; it < 8; it++) {               // B: 1024 x 16B
            int i   = tid + it * 128;
            int row = i >> 3, ch = i & 7;
            uint32_t dst = sB + SWZ(row * 128 + ch * 16);
            const __half* src = Bp + (size_t)row * C + k0 + ch * 8;
            asm volatile("cp.async.cg.shared.global [%0], [%1], 16;" :: "r"(dst), "l"(src));
        }
        asm volatile("cp.async.commit_group;");
    };

    float acc[4][8][4];
    #pragma unroll
    for (int mi = 0; mi < 4; mi++)
        #pragma unroll
        for (int ni = 0; ni < 8; ni++)
            #pragma unroll
            for (int r = 0; r < 4; r++) acc[mi][ni][r] = 0.f;

    issue(0); issue(1);

    for (int kc = 0; kc < KT; kc++) {
        if (kc < KT - 1) { WAITG(1); }   // stage kc complete (1 newer group may pend)
        else             { WAITG(0); }
        __syncthreads();                 // data visible + all warps done reading stage (kc-1)%3
        if (kc + 2 < KT) issue(kc + 2);  // writes stage (kc-1)%3 — safe after the sync

        const uint32_t sA = sb + (kc % STAGES) * STAGE_BYTES;
        const uint32_t sB = sA + A_BYTES;

        #pragma unroll
        for (int ks = 0; ks < 4; ks++) {
            const int kb = ks * 32;
            uint32_t a[4][4], b[8][2];
            #pragma unroll
            for (int mi = 0; mi < 4; mi++) {
                uint32_t addr = sA + SWZ((wm * 64 + mi * 16 + arow) * 128 + kb + akof);
                asm volatile("ldmatrix.sync.aligned.m8n8.x4.shared.b16 {%0,%1,%2,%3}, [%4];"
                             : "=r"(a[mi][0]), "=r"(a[mi][1]), "=r"(a[mi][2]), "=r"(a[mi][3])
                             : "r"(addr));
            }
            #pragma unroll
            for (int nj = 0; nj < 4; nj++) {
                uint32_t addr = sB + SWZ((wn * 64 + nj * 16 + brow) * 128 + kb + bkof);
                asm volatile("ldmatrix.sync.aligned.m8n8.x4.shared.b16 {%0,%1,%2,%3}, [%4];"
                             : "=r"(b[nj*2][0]), "=r"(b[nj*2][1]),
                               "=r"(b[nj*2+1][0]), "=r"(b[nj*2+1][1])
                             : "r"(addr));
            }
            #pragma unroll
            for (int mi = 0; mi < 4; mi++)
                #pragma unroll
                for (int ni = 0; ni < 8; ni++) {
                    asm volatile(
                        "mma.sync.aligned.m16n8k16.row.col.f32.f16.f16.f32 "
                        "{%0,%1,%2,%3}, {%4,%5,%6,%7}, {%8,%9}, {%0,%1,%2,%3};"
                        : "+f"(acc[mi][ni][0]), "+f"(acc[mi][ni][1]),
                          "+f"(acc[mi][ni][2]), "+f"(acc[mi][ni][3])
                        : "r"(a[mi][0]), "r"(a[mi][1]), "r"(a[mi][2]), "r"(a[mi][3]),
                          "r"(b[ni][0]), "r"(b[ni][1]));
                }
        }
    }

    // -------- fused epilogue: column sum of squares over this CTA's 128 rows --------
    const int way = m0 / MS;
    float* cs = colsum + ((size_t)t * WAY + way) * NPAD + n0;
    #pragma unroll
    for (int ni = 0; ni < 8; ni++) {
        float v0 = 0.f, v1 = 0.f;
        #pragma unroll
        for (int mi = 0; mi < 4; mi++) {
            v0 += acc[mi][ni][0] * acc[mi][ni][0] + acc[mi][ni][2] * acc[mi][ni][2];
            v1 += acc[mi][ni][1] * acc[mi][ni][1] + acc[mi][ni][3] * acc[mi][ni][3];
        }
        #pragma unroll
        for (int o = 4; o < 32; o <<= 1) {
            v0 += __shfl_xor_sync(~0u, v0, o);
            v1 += __shfl_xor_sync(~0u, v1, o);
        }
        if (gid == 0) {
            int col = wn * 64 + ni * 8 + tig * 2;
            atomicAdd(&cs[col], v0);
            atomicAdd(&cs[col + 1], v1);
        }
    }
}

// ---------------- kernel 4: /99, LeakyReLU(0.2), conv1d(k=stride=100), +bias ----------------
__global__ void final_kernel(const float* __restrict__ colsum, const float* __restrict__ cw,
                             const float* __restrict__ cb, float* __restrict__ out) {
    int wid  = (blockIdx.x * blockDim.x + threadIdx.x) >> 5;
    int lane = threadIdx.x & 31;
    if (wid >= T * WQ * WAY) return;
    int w = wid % WAY;
    int q = (wid / WAY) % WQ;
    int t = wid / (WAY * WQ);
    const float* cs = colsum + ((size_t)t * WAY + w) * NPAD + q * HW;
    float v = 0.f;
    #pragma unroll
    for (int i = 0; i < 4; i++) {
        int n = lane + 32 * i;
        if (n < HW) {
            float x = cs[n] * (1.0f / 99.0f);
            x = (x >= 0.f) ? x : 0.2f * x;
            v += x * cw[n];
        }
    }
    #pragma unroll
    for (int o = 16; o; o >>= 1) v += __shfl_xor_sync(~0u, v, o);
    if (!lane) out[wid] = v + cb[0];
}

// ---------------- launch (R10 single-stream schedule) ----------------
extern "C" void kernel_launch(void* const* d_in, const int* in_sizes, int n_in,
                              void* d_out, int out_size) {
    const float* qf = (const float*)d_in[0];
    const float* sf = (const float*)d_in[1];
    const float* cw = (const float*)d_in[2];
    const float* cb = (const float*)d_in[3];
    float* out = (float*)d_out;

    __half *dS, *dQ;
    float *dMS, *dCS;
    cudaGetSymbolAddress((void**)&dS,  g_S16);
    cudaGetSymbolAddress((void**)&dQ,  g_Q16);
    cudaGetSymbolAddress((void**)&dMS, g_meanS);
    cudaGetSymbolAddress((void**)&dCS, g_colsum);

    // 1) support means (small; must precede S-centering)
    {
        int warps = T * WAY * C;
        means_s_kernel<<<(warps * 32 + 255) / 256, 256>>>(sf, dMS);
    }
    // 2) merged: center_s + center_q + pads + zero colsum (vectorized)
    merged_prep_kernel<<<MERGED_BLOCKS, 256>>>(sf, qf, dMS, dS, dQ, dCS);
    // 3) GEMM + fused sum-of-squares (tail-friendly grid: 4720 = 15*296 + 280)
    cudaFuncSetAttribute(gemm_hmma_kernel, cudaFuncAttributeMaxDynamicSharedMemorySize, SMEM_TOTAL);
    dim3 grid(NPAD / BN, MTOT / BM, T);   // (59, 20, 4)
    gemm_hmma_kernel<<<grid, 128, SMEM_TOTAL>>>(dS, dQ, dCS);
    // 4) final score
    int warps = T * WQ * WAY;
    final_kernel<<<(warps * 32 + 255) / 256, 256>>>(dCS, cw, cb, out);
}

// round 14
// speedup vs baseline: 1.0878x; 1.0055x over previous
#include <cuda_runtime.h>
#include <cuda_fp16.h>
#include <cstdint>
#include <cstddef>

// ---------------- problem constants ----------------
#define T     4
#define WQ    75
#define WAY   5
#define SHOT  5
#define WS    (WAY*SHOT)        // 25
#define C     640
#define HW    100
#define MS    512               // padded rows per way (500 real + 12 zero)
#define MTOT  (WAY*MS)          // 2560
#define NQ    (WQ*HW)           // 7500
#define NPAD  7552              // 59 * 128 -> grid 4720 = 15*296 + 280 (good tail)
#define BM    128
#define BN    128
#define BKH   64                // K halves per chunk => 128B smem rows
#define KT    (C/BKH)           // 10
#define STAGES 3

#define A_BYTES    (BM*128)     // 16384
#define B_BYTES    (BN*128)     // 16384
#define STAGE_BYTES (A_BYTES + B_BYTES)              // 32768
#define SMEM_TOTAL  (STAGES*STAGE_BYTES)             // 98304

#define SWZ(o) ((o) ^ (((o) >> 3) & 0x70))
#define WAITG(n) asm volatile("cp.async.wait_group %0;" :: "n"(n))

__device__ __forceinline__ uint32_t smem_u32(const void* p) {
    uint32_t a;
    asm("{ .reg .u64 t; cvta.to.shared.u64 t, %1; cvt.u32.u64 %0, t; }" : "=r"(a) : "l"(p));
    return a;
}

// ---------------- scratch (__device__ globals) ----------------
__device__ __align__(256) __half g_S16[(size_t)T * MTOT * C];   // 13.1 MB
__device__ __align__(256) __half g_Q16[(size_t)T * NPAD * C];   // 38.7 MB
__device__ __align__(16) float g_colsum[T * WAY * NPAD];

// ---------------- kernel 1: MERGED prep (fused-mean center_s + center_q + pads + zero) ----
// block ranges:
//   [0,400)                 CS2: support, block = (t, way, 32-ch chunk), all 5 shots,
//                           in-block mean over 500 samples, center, transpose -> fp16
//   [400,3400)              CQ : query, block = (t, q, 64-ch chunk) (R10 verbatim)
//   [3400,3700)             zero S padding rows
//   [3700,3960)             zero Q padding rows
//   [3960,4108)             zero colsum
#define CS2_BLOCKS 400
#define CQ_BLOCKS  (T * WQ * (C/64))     // 3000
#define NS_PAD     (T * WAY * (MS - SHOT*HW) * (C/2))   // 76800 half2
#define NQ_PAD     (T * (NPAD - NQ) * (C/2))            // 66560 half2
#define NSP_BLOCKS (NS_PAD / 256)        // 300
#define NQP_BLOCKS (NQ_PAD / 256)        // 260
#define CSZ_ELEMS  (T * WAY * NPAD / 4)  // 37760 float4
#define CSZ_BLOCKS ((CSZ_ELEMS + 255) / 256)  // 148
#define MERGED_BLOCKS (CS2_BLOCKS + CQ_BLOCKS + NSP_BLOCKS + NQP_BLOCKS + CSZ_BLOCKS)

#define CS2_STRIDE 501                   // odd stride: conflict-light transposed reads
#define PREP_SMEM  (32 * CS2_STRIDE * 4) // 64128 bytes

__global__ void __launch_bounds__(256) merged_prep_kernel(
        const float* __restrict__ sf, const float* __restrict__ qf,
        __half* __restrict__ S, __half* __restrict__ Q, float* __restrict__ cs) {
    extern __shared__ float dynsm[];     // CS2: 32 x 501 f32 ; CQ: 64 x 101 f32 view
    __shared__ float mean[64];
    int b = blockIdx.x;
    int tid = threadIdx.x;
    int warp = tid >> 5, lane = tid & 31;

    if (b < CS2_BLOCKS) {
        // ---- support: fused mean + center + transpose, 32 channels x 500 samples ----
        int cK  = b % (C / 32);          // 0..19
        int way = (b / (C / 32)) % WAY;
        int t   = b / ((C / 32) * WAY);
        int c0  = cK * 32;
        // load 5 shots: each a contiguous 32x100 f32 span
        #pragma unroll
        for (int sh = 0; sh < SHOT; sh++) {
            const float* src = sf + ((size_t)((t * WAY + way) * SHOT + sh) * C + c0) * HW;
            #pragma unroll
            for (int it = 0; it < 4; it++) {
                int idx4 = tid + it * 256;
                if (idx4 < 800) {        // 32 ch * 25 float4
                    float4 v = reinterpret_cast<const float4*>(src)[idx4];
                    int c = idx4 / 25, col = (idx4 % 25) * 4 + sh * HW;
                    float* tr = &dynsm[c * CS2_STRIDE + col];
                    tr[0] = v.x; tr[1] = v.y; tr[2] = v.z; tr[3] = v.w;
                }
            }
        }
        __syncthreads();
        // per-channel mean over all 500 samples
        #pragma unroll
        for (int c = warp; c < 32; c += 8) {
            const float* row = &dynsm[c * CS2_STRIDE];
            float v = 0.f;
            #pragma unroll
            for (int j = 0; j < 16; j++) {
                int idx = lane + j * 32;
                if (idx < 500) v += row[idx];
            }
            #pragma unroll
            for (int o = 16; o; o >>= 1) v += __shfl_xor_sync(~0u, v, o);
            if (!lane) mean[c] = v * (1.0f / (SHOT * HW));
        }
        __syncthreads();
        // centered transposed write: row j = way*512 + j, half2 over channels c0..c0+31
        __half2* dst = (__half2*)(S + ((size_t)t * MTOT + way * MS) * C + c0);
        for (int i = tid; i < 500 * 16; i += 256) {
            int j = i / 16, cp = i % 16;
            int c = cp * 2;
            float v0 = dynsm[c * CS2_STRIDE + j] - mean[c];
            float v1 = dynsm[(c + 1) * CS2_STRIDE + j] - mean[c + 1];
            dst[(size_t)j * (C / 2) + cp] = __floats2half2_rn(v0, v1);
        }
    } else if (b < CS2_BLOCKS + CQ_BLOCKS) {
        // ---- query: fused mean + center + transpose (R10 verbatim, dynsm view 64x101) ----
        float* tile = dynsm;
        int bb = b - CS2_BLOCKS;
        int cc = bb % (C / 64);
        int q  = (bb / (C / 64)) % WQ;
        int t  = bb / ((C / 64) * WQ);
        int c0 = cc * 64;
        const float* src = qf + ((size_t)(t * WQ + q) * C + c0) * HW;
        #pragma unroll
        for (int i = 0; i < 25; i++) {
            int idx = tid + i * 256;
            tile[(idx / 100) * 101 + (idx % 100)] = src[idx];
        }
        __syncthreads();
        #pragma unroll
        for (int r = warp; r < 64; r += 8) {
            const float* row = &tile[r * 101];
            float v = row[lane] + row[lane + 32] + row[lane + 64];
            if (lane < 4) v += row[lane + 96];
            #pragma unroll
            for (int o = 16; o; o >>= 1) v += __shfl_xor_sync(~0u, v, o);
            if (!lane) mean[r] = v * (1.0f / HW);
        }
        __syncthreads();
        __half2* dst = (__half2*)(Q + ((size_t)t * NPAD + q * HW) * C + c0);
        for (int i = tid; i < 32 * HW; i += 256) {
            int n = i / 32, cp = i % 32;
            float v0 = tile[(cp * 2) * 101 + n] - mean[cp * 2];
            float v1 = tile[(cp * 2 + 1) * 101 + n] - mean[cp * 2 + 1];
            dst[(size_t)n * (C / 2) + cp] = __floats2half2_rn(v0, v1);
        }
    } else if (b < CS2_BLOCKS + CQ_BLOCKS + NSP_BLOCKS) {
        // ---- zero S padding rows ----
        int i = (b - CS2_BLOCKS - CQ_BLOCKS) * 256 + tid;
        int cp = i % (C / 2);
        int r  = (i / (C / 2)) % (MS - SHOT * HW);
        int wy = (i / ((C / 2) * (MS - SHOT * HW))) % WAY;
        int t  = i / ((C / 2) * (MS - SHOT * HW) * WAY);
        ((__half2*)S)[((size_t)t * MTOT + wy * MS + SHOT * HW + r) * (C / 2) + cp] =
            __floats2half2_rn(0.f, 0.f);
    } else if (b < CS2_BLOCKS + CQ_BLOCKS + NSP_BLOCKS + NQP_BLOCKS) {
        // ---- zero Q padding rows ----
        int i = (b - CS2_BLOCKS - CQ_BLOCKS - NSP_BLOCKS) * 256 + tid;
        int cp = i % (C / 2);
        int r  = (i / (C / 2)) % (NPAD - NQ);
        int t  = i / ((C / 2) * (NPAD - NQ));
        ((__half2*)Q)[((size_t)t * NPAD + NQ + r) * (C / 2) + cp] =
            __floats2half2_rn(0.f, 0.f);
    } else {
        // ---- zero colsum ----
        int i = (b - CS2_BLOCKS - CQ_BLOCKS - NSP_BLOCKS - NQP_BLOCKS) * 256 + tid;
        if (i < CSZ_ELEMS)
            ((float4*)cs)[i] = make_float4(0.f, 0.f, 0.f, 0.f);
    }
}

// ---------------- kernel 2: fp16 HMMA GEMM (128x128) + fused column sum-of-squares ----------------
// R7/R10 config: 128 threads (4 warps 2x2), warp tile 64x64, 2 CTAs/SM, 3 stages.
__global__ void __launch_bounds__(128, 2) gemm_hmma_kernel(const __half* __restrict__ A,
                                                           const __half* __restrict__ B,
                                                           float* __restrict__ colsum) {
    extern __shared__ char smem[];
    const uint32_t sb = smem_u32(smem);

    const int tid  = threadIdx.x;
    const int warp = tid >> 5, lane = tid & 31;
    const int wm = warp & 1;          // 0..1 : 64-row half (M)
    const int wn = warp >> 1;         // 0..1 : 64-col half (N)
    const int gid = lane >> 2, tig = lane & 3;

    const int t  = blockIdx.z;
    const int m0 = blockIdx.y * BM;
    const int n0 = blockIdx.x * BN;
    const __half* Ap = A + ((size_t)t * MTOT + m0) * C;
    const __half* Bp = B + ((size_t)t * NPAD + n0) * C;

    const int arow = lane & 15;
    const int akof = (lane >> 4) * 16;
    const int brow = ((lane >> 4) << 3) | (lane & 7);
    const int bkof = ((lane >> 3) & 1) * 16;

    auto issue = [&](int kc) {
        const int s  = kc % STAGES;
        const int k0 = kc * BKH;
        const uint32_t sA = sb + s * STAGE_BYTES;
        const uint32_t sB = sA + A_BYTES;
        #pragma unroll
        for (int it = 0; it < 8; it++) {               // A: 1024 x 16B
            int i   = tid + it * 128;
            int row = i >> 3, ch = i & 7;
            uint32_t dst = sA + SWZ(row * 128 + ch * 16);
            const __half* src = Ap + (size_t)row * C + k0 + ch * 8;
            asm volatile("cp.async.cg.shared.global [%0], [%1], 16;" :: "r"(dst), "l"(src));
        }
        #pragma unroll
        for (int it = 0; it < 8; it++) {               // B: 1024 x 16B
            int i   = tid + it * 128;
            int row = i >> 3, ch = i & 7;
            uint32_t dst = sB + SWZ(row * 128 + ch * 16);
            const __half* src = Bp + (size_t)row * C + k0 + ch * 8;
            asm volatile("cp.async.cg.shared.global [%0], [%1], 16;" :: "r"(dst), "l"(src));
        }
        asm volatile("cp.async.commit_group;");
    };

    float acc[4][8][4];
    #pragma unroll
    for (int mi = 0; mi < 4; mi++)
        #pragma unroll
        for (int ni = 0; ni < 8; ni++)
            #pragma unroll
            for (int r = 0; r < 4; r++) acc[mi][ni][r] = 0.f;

    issue(0); issue(1);

    for (int kc = 0; kc < KT; kc++) {
        if (kc < KT - 1) { WAITG(1); }   // stage kc complete (1 newer group may pend)
        else             { WAITG(0); }
        __syncthreads();                 // data visible + all warps done reading stage (kc-1)%3
        if (kc + 2 < KT) issue(kc + 2);  // writes stage (kc-1)%3 — safe after the sync

        const uint32_t sA = sb + (kc % STAGES) * STAGE_BYTES;
        const uint32_t sB = sA + A_BYTES;

        #pragma unroll
        for (int ks = 0; ks < 4; ks++) {
            const int kb = ks * 32;
            uint32_t a[4][4], b[8][2];
            #pragma unroll
            for (int mi = 0; mi < 4; mi++) {
                uint32_t addr = sA + SWZ((wm * 64 + mi * 16 + arow) * 128 + kb + akof);
                asm volatile("ldmatrix.sync.aligned.m8n8.x4.shared.b16 {%0,%1,%2,%3}, [%4];"
                             : "=r"(a[mi][0]), "=r"(a[mi][1]), "=r"(a[mi][2]), "=r"(a[mi][3])
                             : "r"(addr));
            }
            #pragma unroll
            for (int nj = 0; nj < 4; nj++) {
                uint32_t addr = sB + SWZ((wn * 64 + nj * 16 + brow) * 128 + kb + bkof);
                asm volatile("ldmatrix.sync.aligned.m8n8.x4.shared.b16 {%0,%1,%2,%3}, [%4];"
                             : "=r"(b[nj*2][0]), "=r"(b[nj*2][1]),
                               "=r"(b[nj*2+1][0]), "=r"(b[nj*2+1][1])
                             : "r"(addr));
            }
            #pragma unroll
            for (int mi = 0; mi < 4; mi++)
                #pragma unroll
                for (int ni = 0; ni < 8; ni++) {
                    asm volatile(
                        "mma.sync.aligned.m16n8k16.row.col.f32.f16.f16.f32 "
                        "{%0,%1,%2,%3}, {%4,%5,%6,%7}, {%8,%9}, {%0,%1,%2,%3};"
                        : "+f"(acc[mi][ni][0]), "+f"(acc[mi][ni][1]),
                          "+f"(acc[mi][ni][2]), "+f"(acc[mi][ni][3])
                        : "r"(a[mi][0]), "r"(a[mi][1]), "r"(a[mi][2]), "r"(a[mi][3]),
                          "r"(b[ni][0]), "r"(b[ni][1]));
                }
        }
    }

    // -------- fused epilogue: column sum of squares over this CTA's 128 rows --------
    const int way = m0 / MS;
    float* cs = colsum + ((size_t)t * WAY + way) * NPAD + n0;
    #pragma unroll
    for (int ni = 0; ni < 8; ni++) {
        float v0 = 0.f, v1 = 0.f;
        #pragma unroll
        for (int mi = 0; mi < 4; mi++) {
            v0 += acc[mi][ni][0] * acc[mi][ni][0] + acc[mi][ni][2] * acc[mi][ni][2];
            v1 += acc[mi][ni][1] * acc[mi][ni][1] + acc[mi][ni][3] * acc[mi][ni][3];
        }
        #pragma unroll
        for (int o = 4; o < 32; o <<= 1) {
            v0 += __shfl_xor_sync(~0u, v0, o);
            v1 += __shfl_xor_sync(~0u, v1, o);
        }
        if (gid == 0) {
            int col = wn * 64 + ni * 8 + tig * 2;
            atomicAdd(&cs[col], v0);
            atomicAdd(&cs[col + 1], v1);
        }
    }
}

// ---------------- kernel 3: /99, LeakyReLU(0.2), conv1d(k=stride=100), +bias ----------------
__global__ void final_kernel(const float* __restrict__ colsum, const float* __restrict__ cw,
                             const float* __restrict__ cb, float* __restrict__ out) {
    int wid  = (blockIdx.x * blockDim.x + threadIdx.x) >> 5;
    int lane = threadIdx.x & 31;
    if (wid >= T * WQ * WAY) return;
    int w = wid % WAY;
    int q = (wid / WAY) % WQ;
    int t = wid / (WAY * WQ);
    const float* cs = colsum + ((size_t)t * WAY + w) * NPAD + q * HW;
    float v = 0.f;
    #pragma unroll
    for (int i = 0; i < 4; i++) {
        int n = lane + 32 * i;
        if (n < HW) {
            float x = cs[n] * (1.0f / 99.0f);
            x = (x >= 0.f) ? x : 0.2f * x;
            v += x * cw[n];
        }
    }
    #pragma unroll
    for (int o = 16; o; o >>= 1) v += __shfl_xor_sync(~0u, v, o);
    if (!lane) out[wid] = v + cb[0];
}

// ---------------- launch (3 kernels) ----------------
extern "C" void kernel_launch(void* const* d_in, const int* in_sizes, int n_in,
                              void* d_out, int out_size) {
    const float* qf = (const float*)d_in[0];
    const float* sf = (const float*)d_in[1];
    const float* cw = (const float*)d_in[2];
    const float* cb = (const float*)d_in[3];
    float* out = (float*)d_out;

    __half *dS, *dQ;
    float *dCS;
    cudaGetSymbolAddress((void**)&dS,  g_S16);
    cudaGetSymbolAddress((void**)&dQ,  g_Q16);
    cudaGetSymbolAddress((void**)&dCS, g_colsum);

    // 1) merged prep: fused-mean center_s + center_q + pads + zero colsum
    cudaFuncSetAttribute(merged_prep_kernel, cudaFuncAttributeMaxDynamicSharedMemorySize, PREP_SMEM);
    merged_prep_kernel<<<MERGED_BLOCKS, 256, PREP_SMEM>>>(sf, qf, dS, dQ, dCS);
    // 2) GEMM + fused sum-of-squares
    cudaFuncSetAttribute(gemm_hmma_kernel, cudaFuncAttributeMaxDynamicSharedMemorySize, SMEM_TOTAL);
    dim3 grid(NPAD / BN, MTOT / BM, T);   // (59, 20, 4)
    gemm_hmma_kernel<<<grid, 128, SMEM_TOTAL>>>(dS, dQ, dCS);
    // 3) final score
    int warps = T * WQ * WAY;
    final_kernel<<<(warps * 32 + 255) / 256, 256>>>(dCS, cw, cb, out);
}

// round 15
// speedup vs baseline: 1.0979x; 1.0093x over previous
#include <cuda_runtime.h>
#include <cuda_fp16.h>
#include <cstdint>
#include <cstddef>

// ---------------- problem constants ----------------
#define T     4
#define WQ    75
#define WAY   5
#define SHOT  5
#define WS    (WAY*SHOT)        // 25
#define C     640
#define HW    100
#define MS    512               // padded rows per way (500 real + 12 zero)
#define MTOT  (WAY*MS)          // 2560
#define NQ    (WQ*HW)           // 7500
#define NPAD  7552              // 59 * 128 -> grid 4720 = 15*296 + 280 (good tail)
#define BM    128
#define BN    128
#define BKH   64                // K halves per chunk => 128B smem rows
#define KT    (C/BKH)           // 10
#define STAGES 3

#define A_BYTES    (BM*128)     // 16384
#define B_BYTES    (BN*128)     // 16384
#define STAGE_BYTES (A_BYTES + B_BYTES)              // 32768
#define SMEM_TOTAL  (STAGES*STAGE_BYTES)             // 98304

#define SWZ(o) ((o) ^ (((o) >> 3) & 0x70))
#define WAITG(n) asm volatile("cp.async.wait_group %0;" :: "n"(n))

__device__ __forceinline__ uint32_t smem_u32(const void* p) {
    uint32_t a;
    asm("{ .reg .u64 t; cvta.to.shared.u64 t, %1; cvt.u32.u64 %0, t; }" : "=r"(a) : "l"(p));
    return a;
}

// ---------------- scratch (__device__ globals) ----------------
__device__ __align__(256) __half g_S16[(size_t)T * MTOT * C];   // 13.1 MB
__device__ __align__(256) __half g_Q16[(size_t)T * NPAD * C];   // 38.7 MB
__device__ __align__(16) float g_colsum[T * WAY * NPAD];

// ---------------- kernel A: support fused-mean center+transpose (heavy smem, 400 blocks) ----
#define CS2_BLOCKS 400
#define CS2_STRIDE 501                   // odd stride: conflict-light transposed reads
#define PREP_SMEM  (32 * CS2_STRIDE * 4) // 64128 bytes

__global__ void __launch_bounds__(256) center_s_kernel(
        const float* __restrict__ sf, __half* __restrict__ S) {
    extern __shared__ float dynsm[];     // 32 x 501 f32
    __shared__ float mean[32];
    int b = blockIdx.x;
    int tid = threadIdx.x;
    int warp = tid >> 5, lane = tid & 31;

    int cK  = b % (C / 32);              // 0..19
    int way = (b / (C / 32)) % WAY;
    int t   = b / ((C / 32) * WAY);
    int c0  = cK * 32;
    // load 5 shots: each a contiguous 32x100 f32 span
    #pragma unroll
    for (int sh = 0; sh < SHOT; sh++) {
        const float* src = sf + ((size_t)((t * WAY + way) * SHOT + sh) * C + c0) * HW;
        #pragma unroll
        for (int it = 0; it < 4; it++) {
            int idx4 = tid + it * 256;
            if (idx4 < 800) {            // 32 ch * 25 float4
                float4 v = reinterpret_cast<const float4*>(src)[idx4];
                int c = idx4 / 25, col = (idx4 % 25) * 4 + sh * HW;
                float* tr = &dynsm[c * CS2_STRIDE + col];
                tr[0] = v.x; tr[1] = v.y; tr[2] = v.z; tr[3] = v.w;
            }
        }
    }
    __syncthreads();
    // per-channel mean over all 500 samples
    #pragma unroll
    for (int c = warp; c < 32; c += 8) {
        const float* row = &dynsm[c * CS2_STRIDE];
        float v = 0.f;
        #pragma unroll
        for (int j = 0; j < 16; j++) {
            int idx = lane + j * 32;
            if (idx < 500) v += row[idx];
        }
        #pragma unroll
        for (int o = 16; o; o >>= 1) v += __shfl_xor_sync(~0u, v, o);
        if (!lane) mean[c] = v * (1.0f / (SHOT * HW));
    }
    __syncthreads();
    // centered transposed write: row j = way*512 + j, half2 over channels c0..c0+31
    __half2* dst = (__half2*)(S + ((size_t)t * MTOT + way * MS) * C + c0);
    for (int i = tid; i < 500 * 16; i += 256) {
        int j = i / 16, cp = i % 16;
        int c = cp * 2;
        float v0 = dynsm[c * CS2_STRIDE + j] - mean[c];
        float v1 = dynsm[(c + 1) * CS2_STRIDE + j] - mean[c + 1];
        dst[(size_t)j * (C / 2) + cp] = __floats2half2_rn(v0, v1);
    }
}

// ---------------- kernel B: query center + pads + colsum-zero (light smem, high occ) ----
#define CQ_BLOCKS  (T * WQ * (C/64))     // 3000
#define NS_PAD     (T * WAY * (MS - SHOT*HW) * (C/2))   // 76800 half2
#define NQ_PAD     (T * (NPAD - NQ) * (C/2))            // 66560 half2
#define NSP_BLOCKS (NS_PAD / 256)        // 300
#define NQP_BLOCKS (NQ_PAD / 256)        // 260
#define CSZ_ELEMS  (T * WAY * NPAD / 4)  // 37760 float4
#define CSZ_BLOCKS ((CSZ_ELEMS + 255) / 256)  // 148
#define PREPB_BLOCKS (CQ_BLOCKS + NSP_BLOCKS + NQP_BLOCKS + CSZ_BLOCKS)

__global__ void __launch_bounds__(256) prep_b_kernel(
        const float* __restrict__ qf,
        __half* __restrict__ S, __half* __restrict__ Q, float* __restrict__ cs) {
    __shared__ float tile[64 * 101];
    __shared__ float mean[64];
    int b = blockIdx.x;
    int tid = threadIdx.x;

    if (b < CQ_BLOCKS) {
        // ---- query: fused mean + center + transpose (R10 verbatim) ----
        int cc = b % (C / 64);
        int q  = (b / (C / 64)) % WQ;
        int t  = b / ((C / 64) * WQ);
        int c0 = cc * 64;
        const float* src = qf + ((size_t)(t * WQ + q) * C + c0) * HW;
        int warp = tid >> 5, lane = tid & 31;
        #pragma unroll
        for (int i = 0; i < 25; i++) {
            int idx = tid + i * 256;
            tile[(idx / 100) * 101 + (idx % 100)] = src[idx];
        }
        __syncthreads();
        #pragma unroll
        for (int r = warp; r < 64; r += 8) {
            const float* row = &tile[r * 101];
            float v = row[lane] + row[lane + 32] + row[lane + 64];
            if (lane < 4) v += row[lane + 96];
            #pragma unroll
            for (int o = 16; o; o >>= 1) v += __shfl_xor_sync(~0u, v, o);
            if (!lane) mean[r] = v * (1.0f / HW);
        }
        __syncthreads();
        __half2* dst = (__half2*)(Q + ((size_t)t * NPAD + q * HW) * C + c0);
        for (int i = tid; i < 32 * HW; i += 256) {
            int n = i / 32, cp = i % 32;
            float v0 = tile[(cp * 2) * 101 + n] - mean[cp * 2];
            float v1 = tile[(cp * 2 + 1) * 101 + n] - mean[cp * 2 + 1];
            dst[(size_t)n * (C / 2) + cp] = __floats2half2_rn(v0, v1);
        }
    } else if (b < CQ_BLOCKS + NSP_BLOCKS) {
        // ---- zero S padding rows ----
        int i = (b - CQ_BLOCKS) * 256 + tid;
        int cp = i % (C / 2);
        int r  = (i / (C / 2)) % (MS - SHOT * HW);
        int wy = (i / ((C / 2) * (MS - SHOT * HW))) % WAY;
        int t  = i / ((C / 2) * (MS - SHOT * HW) * WAY);
        ((__half2*)S)[((size_t)t * MTOT + wy * MS + SHOT * HW + r) * (C / 2) + cp] =
            __floats2half2_rn(0.f, 0.f);
    } else if (b < CQ_BLOCKS + NSP_BLOCKS + NQP_BLOCKS) {
        // ---- zero Q padding rows ----
        int i = (b - CQ_BLOCKS - NSP_BLOCKS) * 256 + tid;
        int cp = i % (C / 2);
        int r  = (i / (C / 2)) % (NPAD - NQ);
        int t  = i / ((C / 2) * (NPAD - NQ));
        ((__half2*)Q)[((size_t)t * NPAD + NQ + r) * (C / 2) + cp] =
            __floats2half2_rn(0.f, 0.f);
    } else {
        // ---- zero colsum ----
        int i = (b - CQ_BLOCKS - NSP_BLOCKS - NQP_BLOCKS) * 256 + tid;
        if (i < CSZ_ELEMS)
            ((float4*)cs)[i] = make_float4(0.f, 0.f, 0.f, 0.f);
    }
}

// ---------------- kernel 3: fp16 HMMA GEMM (128x128) + fused column sum-of-squares ----------------
// R7/R10 config: 128 threads (4 warps 2x2), warp tile 64x64, 2 CTAs/SM, 3 stages.
__global__ void __launch_bounds__(128, 2) gemm_hmma_kernel(const __half* __restrict__ A,
                                                           const __half* __restrict__ B,
                                                           float* __restrict__ colsum) {
    extern __shared__ char smem[];
    const uint32_t sb = smem_u32(smem);

    const int tid  = threadIdx.x;
    const int warp = tid >> 5, lane = tid & 31;
    const int wm = warp & 1;          // 0..1 : 64-row half (M)
    const int wn = warp >> 1;         // 0..1 : 64-col half (N)
    const int gid = lane >> 2, tig = lane & 3;

    const int t  = blockIdx.z;
    const int m0 = blockIdx.y * BM;
    const int n0 = blockIdx.x * BN;
    const __half* Ap = A + ((size_t)t * MTOT + m0) * C;
    const __half* Bp = B + ((size_t)t * NPAD + n0) * C;

    const int arow = lane & 15;
    const int akof = (lane >> 4) * 16;
    const int brow = ((lane >> 4) << 3) | (lane & 7);
    const int bkof = ((lane >> 3) & 1) * 16;

    auto issue = [&](int kc) {
        const int s  = kc % STAGES;
        const int k0 = kc * BKH;
        const uint32_t sA = sb + s * STAGE_BYTES;
        const uint32_t sB = sA + A_BYTES;
        #pragma unroll
        for (int it = 0; it < 8; it++) {               // A: 1024 x 16B
            int i   = tid + it * 128;
            int row = i >> 3, ch = i & 7;
            uint32_t dst = sA + SWZ(row * 128 + ch * 16);
            const __half* src = Ap + (size_t)row * C + k0 + ch * 8;
            asm volatile("cp.async.cg.shared.global [%0], [%1], 16;" :: "r"(dst), "l"(src));
        }
        #pragma unroll
        for (int it = 0; it < 8; it++) {               // B: 1024 x 16B
            int i   = tid + it * 128;
            int row = i >> 3, ch = i & 7;
            uint32_t dst = sB + SWZ(row * 128 + ch * 16);
            const __half* src = Bp + (size_t)row * C + k0 + ch * 8;
            asm volatile("cp.async.cg.shared.global [%0], [%1], 16;" :: "r"(dst), "l"(src));
        }
        asm volatile("cp.async.commit_group;");
    };

    float acc[4][8][4];
    #pragma unroll
    for (int mi = 0; mi < 4; mi++)
        #pragma unroll
        for (int ni = 0; ni < 8; ni++)
            #pragma unroll
            for (int r = 0; r < 4; r++) acc[mi][ni][r] = 0.f;

    issue(0); issue(1);

    for (int kc = 0; kc < KT; kc++) {
        if (kc < KT - 1) { WAITG(1); }   // stage kc complete (1 newer group may pend)
        else             { WAITG(0); }
        __syncthreads();                 // data visible + all warps done reading stage (kc-1)%3
        if (kc + 2 < KT) issue(kc + 2);  // writes stage (kc-1)%3 — safe after the sync

        const uint32_t sA = sb + (kc % STAGES) * STAGE_BYTES;
        const uint32_t sB = sA + A_BYTES;

        #pragma unroll
        for (int ks = 0; ks < 4; ks++) {
            const int kb = ks * 32;
            uint32_t a[4][4], b[8][2];
            #pragma unroll
            for (int mi = 0; mi < 4; mi++) {
                uint32_t addr = sA + SWZ((wm * 64 + mi * 16 + arow) * 128 + kb + akof);
                asm volatile("ldmatrix.sync.aligned.m8n8.x4.shared.b16 {%0,%1,%2,%3}, [%4];"
                             : "=r"(a[mi][0]), "=r"(a[mi][1]), "=r"(a[mi][2]), "=r"(a[mi][3])
                             : "r"(addr));
            }
            #pragma unroll
            for (int nj = 0; nj < 4; nj++) {
                uint32_t addr = sB + SWZ((wn * 64 + nj * 16 + brow) * 128 + kb + bkof);
                asm volatile("ldmatrix.sync.aligned.m8n8.x4.shared.b16 {%0,%1,%2,%3}, [%4];"
                             : "=r"(b[nj*2][0]), "=r"(b[nj*2][1]),
                               "=r"(b[nj*2+1][0]), "=r"(b[nj*2+1][1])
                             : "r"(addr));
            }
            #pragma unroll
            for (int mi = 0; mi < 4; mi++)
                #pragma unroll
                for (int ni = 0; ni < 8; ni++) {
                    asm volatile(
                        "mma.sync.aligned.m16n8k16.row.col.f32.f16.f16.f32 "
                        "{%0,%1,%2,%3}, {%4,%5,%6,%7}, {%8,%9}, {%0,%1,%2,%3};"
                        : "+f"(acc[mi][ni][0]), "+f"(acc[mi][ni][1]),
                          "+f"(acc[mi][ni][2]), "+f"(acc[mi][ni][3])
                        : "r"(a[mi][0]), "r"(a[mi][1]), "r"(a[mi][2]), "r"(a[mi][3]),
                          "r"(b[ni][0]), "r"(b[ni][1]));
                }
        }
    }

    // -------- fused epilogue: column sum of squares over this CTA's 128 rows --------
    const int way = m0 / MS;
    float* cs = colsum + ((size_t)t * WAY + way) * NPAD + n0;
    #pragma unroll
    for (int ni = 0; ni < 8; ni++) {
        float v0 = 0.f, v1 = 0.f;
        #pragma unroll
        for (int mi = 0; mi < 4; mi++) {
            v0 += acc[mi][ni][0] * acc[mi][ni][0] + acc[mi][ni][2] * acc[mi][ni][2];
            v1 += acc[mi][ni][1] * acc[mi][ni][1] + acc[mi][ni][3] * acc[mi][ni][3];
        }
        #pragma unroll
        for (int o = 4; o < 32; o <<= 1) {
            v0 += __shfl_xor_sync(~0u, v0, o);
            v1 += __shfl_xor_sync(~0u, v1, o);
        }
        if (gid == 0) {
            int col = wn * 64 + ni * 8 + tig * 2;
            atomicAdd(&cs[col], v0);
            atomicAdd(&cs[col + 1], v1);
        }
    }
}

// ---------------- kernel 4: /99, LeakyReLU(0.2), conv1d(k=stride=100), +bias ----------------
__global__ void final_kernel(const float* __restrict__ colsum, const float* __restrict__ cw,
                             const float* __restrict__ cb, float* __restrict__ out) {
    int wid  = (blockIdx.x * blockDim.x + threadIdx.x) >> 5;
    int lane = threadIdx.x & 31;
    if (wid >= T * WQ * WAY) return;
    int w = wid % WAY;
    int q = (wid / WAY) % WQ;
    int t = wid / (WAY * WQ);
    const float* cs = colsum + ((size_t)t * WAY + w) * NPAD + q * HW;
    float v = 0.f;
    #pragma unroll
    for (int i = 0; i < 4; i++) {
        int n = lane + 32 * i;
        if (n < HW) {
            float x = cs[n] * (1.0f / 99.0f);
            x = (x >= 0.f) ? x : 0.2f * x;
            v += x * cw[n];
        }
    }
    #pragma unroll
    for (int o = 16; o; o >>= 1) v += __shfl_xor_sync(~0u, v, o);
    if (!lane) out[wid] = v + cb[0];
}

// ---------------- launch (4 kernels) ----------------
extern "C" void kernel_launch(void* const* d_in, const int* in_sizes, int n_in,
                              void* d_out, int out_size) {
    const float* qf = (const float*)d_in[0];
    const float* sf = (const float*)d_in[1];
    const float* cw = (const float*)d_in[2];
    const float* cb = (const float*)d_in[3];
    float* out = (float*)d_out;

    __half *dS, *dQ;
    float *dCS;
    cudaGetSymbolAddress((void**)&dS,  g_S16);
    cudaGetSymbolAddress((void**)&dQ,  g_Q16);
    cudaGetSymbolAddress((void**)&dCS, g_colsum);

    // 1) support fused-mean center+transpose (heavy smem, small grid)
    cudaFuncSetAttribute(center_s_kernel, cudaFuncAttributeMaxDynamicSharedMemorySize, PREP_SMEM);
    center_s_kernel<<<CS2_BLOCKS, 256, PREP_SMEM>>>(sf, dS);
    // 2) query center + pads + zero colsum (light smem, high occupancy)
    prep_b_kernel<<<PREPB_BLOCKS, 256>>>(qf, dS, dQ, dCS);
    // 3) GEMM + fused sum-of-squares
    cudaFuncSetAttribute(gemm_hmma_kernel, cudaFuncAttributeMaxDynamicSharedMemorySize, SMEM_TOTAL);
    dim3 grid(NPAD / BN, MTOT / BM, T);   // (59, 20, 4)
    gemm_hmma_kernel<<<grid, 128, SMEM_TOTAL>>>(dS, dQ, dCS);
    // 4) final score
    int warps = T * WQ * WAY;
    final_kernel<<<(warps * 32 + 255) / 256, 256>>>(dCS, cw, cb, out);
}

// round 16
// speedup vs baseline: 1.1074x; 1.0087x over previous
#include <cuda_runtime.h>
#include <cuda_fp16.h>
#include <cstdint>
#include <cstddef>

// ---------------- problem constants ----------------
#define T     4
#define WQ    75
#define WAY   5
#define SHOT  5
#define WS    (WAY*SHOT)        // 25
#define C     640
#define HW    100
#define MS    512               // padded rows per way (500 real + 12 zero)
#define MTOT  (WAY*MS)          // 2560
#define NQ    (WQ*HW)           // 7500
#define NPAD  7552              // 59 * 128 -> grid 4720 = 15*296 + 280 (good tail)
#define BM    128
#define BN    128
#define BKH   64                // K halves per chunk => 128B smem rows
#define KT    (C/BKH)           // 10
#define STAGES 3

#define A_BYTES    (BM*128)     // 16384
#define B_BYTES    (BN*128)     // 16384
#define STAGE_BYTES (A_BYTES + B_BYTES)              // 32768
#define SMEM_TOTAL  (STAGES*STAGE_BYTES)             // 98304

#define SWZ(o) ((o) ^ (((o) >> 3) & 0x70))
#define WAITG(n) asm volatile("cp.async.wait_group %0;" :: "n"(n))

__device__ __forceinline__ uint32_t smem_u32(const void* p) {
    uint32_t a;
    asm("{ .reg .u64 t; cvta.to.shared.u64 t, %1; cvt.u32.u64 %0, t; }" : "=r"(a) : "l"(p));
    return a;
}

// ---------------- scratch (__device__ globals) ----------------
__device__ __align__(256) __half g_S16[(size_t)T * MTOT * C];   // 13.1 MB
__device__ __align__(256) __half g_Q16[(size_t)T * NPAD * C];   // 38.7 MB
__device__ __align__(16) float g_colsum[T * WAY * NPAD];

// ---------------- kernel 1: UNIFIED prep (uniform 25.9KB smem footprint) ----
// block ranges:
//   [0,200)      CS: support, block = (t, way, 64-ch chunk), two-pass over 5 shots
//                (pass1: mean accumulate; pass2: L2-hit re-read, center, write fp16)
//   [200,3200)   CQ: query fused-mean center+transpose (R10/R15 verbatim)
//   [3200,3500)  zero S padding rows
//   [3500,3760)  zero Q padding rows
//   [3760,3908)  zero colsum
#define CS_BLOCKS  (T * WAY * (C/64))    // 200
#define CQ_BLOCKS  (T * WQ * (C/64))     // 3000
#define NS_PAD     (T * WAY * (MS - SHOT*HW) * (C/2))   // 76800 half2
#define NQ_PAD     (T * (NPAD - NQ) * (C/2))            // 66560 half2
#define NSP_BLOCKS (NS_PAD / 256)        // 300
#define NQP_BLOCKS (NQ_PAD / 256)        // 260
#define CSZ_ELEMS  (T * WAY * NPAD / 4)  // 37760 float4
#define CSZ_BLOCKS ((CSZ_ELEMS + 255) / 256)  // 148
#define MERGED_BLOCKS (CS_BLOCKS + CQ_BLOCKS + NSP_BLOCKS + NQP_BLOCKS + CSZ_BLOCKS)

__global__ void __launch_bounds__(256) prep_kernel(
        const float* __restrict__ sf, const float* __restrict__ qf,
        __half* __restrict__ S, __half* __restrict__ Q, float* __restrict__ cs) {
    __shared__ float tile[64 * 101];
    __shared__ float mean[64];
    int b = blockIdx.x;
    int tid = threadIdx.x;
    int warp = tid >> 5, lane = tid & 31;

    if (b < CS_BLOCKS) {
        // ---- support: two-pass fused-mean center+transpose, 64 ch x 5 shots ----
        int cc  = b % (C / 64);
        int way = (b / (C / 64)) % WAY;
        int t   = b / ((C / 64) * WAY);
        int c0  = cc * 64;
        const float* base = sf + ((size_t)(t * WAY + way) * SHOT) * C * HW;

        if (tid < 64) mean[tid] = 0.f;

        // pass 1: accumulate per-channel sums shot by shot
        for (int sh = 0; sh < SHOT; sh++) {
            __syncthreads();             // mean-init done / prev reduce done
            const float* src = base + ((size_t)sh * C + c0) * HW;
            #pragma unroll
            for (int i = 0; i < 25; i++) {
                int idx = tid + i * 256;
                tile[(idx / 100) * 101 + (idx % 100)] = src[idx];
            }
            __syncthreads();
            #pragma unroll
            for (int r = warp; r < 64; r += 8) {
                const float* row = &tile[r * 101];
                float v = row[lane] + row[lane + 32] + row[lane + 64];
                if (lane < 4) v += row[lane + 96];
                #pragma unroll
                for (int o = 16; o; o >>= 1) v += __shfl_xor_sync(~0u, v, o);
                if (!lane) mean[r] += v;
            }
        }
        __syncthreads();
        if (tid < 64) mean[tid] *= (1.0f / (SHOT * HW));
        __syncthreads();

        // pass 2: center+write. shot 4 is still resident in tile -> write it first.
        auto write_shot = [&](int sh) {
            __half2* dst = (__half2*)(S + ((size_t)t * MTOT + way * MS + sh * HW) * C + c0);
            for (int i = tid; i < 32 * HW; i += 256) {
                int n = i / 32, cp = i % 32;
                float v0 = tile[(cp * 2) * 101 + n] - mean[cp * 2];
                float v1 = tile[(cp * 2 + 1) * 101 + n] - mean[cp * 2 + 1];
                dst[(size_t)n * (C / 2) + cp] = __floats2half2_rn(v0, v1);
            }
        };
        write_shot(SHOT - 1);
        for (int sh = 0; sh < SHOT - 1; sh++) {
            __syncthreads();             // writes of previous shot done before reload
            const float* src = base + ((size_t)sh * C + c0) * HW;
            #pragma unroll
            for (int i = 0; i < 25; i++) {
                int idx = tid + i * 256;
                tile[(idx / 100) * 101 + (idx % 100)] = src[idx];   // L2 hit (sf = 25.6MB)
            }
            __syncthreads();
            write_shot(sh);
        }
    } else if (b < CS_BLOCKS + CQ_BLOCKS) {
        // ---- query: fused mean + center + transpose (R10 verbatim) ----
        int bb = b - CS_BLOCKS;
        int cc = bb % (C / 64);
        int q  = (bb / (C / 64)) % WQ;
        int t  = bb / ((C / 64) * WQ);
        int c0 = cc * 64;
        const float* src = qf + ((size_t)(t * WQ + q) * C + c0) * HW;
        #pragma unroll
        for (int i = 0; i < 25; i++) {
            int idx = tid + i * 256;
            tile[(idx / 100) * 101 + (idx % 100)] = src[idx];
        }
        __syncthreads();
        #pragma unroll
        for (int r = warp; r < 64; r += 8) {
            const float* row = &tile[r * 101];
            float v = row[lane] + row[lane + 32] + row[lane + 64];
            if (lane < 4) v += row[lane + 96];
            #pragma unroll
            for (int o = 16; o; o >>= 1) v += __shfl_xor_sync(~0u, v, o);
            if (!lane) mean[r] = v * (1.0f / HW);
        }
        __syncthreads();
        __half2* dst = (__half2*)(Q + ((size_t)t * NPAD + q * HW) * C + c0);
        for (int i = tid; i < 32 * HW; i += 256) {
            int n = i / 32, cp = i % 32;
            float v0 = tile[(cp * 2) * 101 + n] - mean[cp * 2];
            float v1 = tile[(cp * 2 + 1) * 101 + n] - mean[cp * 2 + 1];
            dst[(size_t)n * (C / 2) + cp] = __floats2half2_rn(v0, v1);
        }
    } else if (b < CS_BLOCKS + CQ_BLOCKS + NSP_BLOCKS) {
        // ---- zero S padding rows ----
        int i = (b - CS_BLOCKS - CQ_BLOCKS) * 256 + tid;
        int cp = i % (C / 2);
        int r  = (i / (C / 2)) % (MS - SHOT * HW);
        int wy = (i / ((C / 2) * (MS - SHOT * HW))) % WAY;
        int t  = i / ((C / 2) * (MS - SHOT * HW) * WAY);
        ((__half2*)S)[((size_t)t * MTOT + wy * MS + SHOT * HW + r) * (C / 2) + cp] =
            __floats2half2_rn(0.f, 0.f);
    } else if (b < CS_BLOCKS + CQ_BLOCKS + NSP_BLOCKS + NQP_BLOCKS) {
        // ---- zero Q padding rows ----
        int i = (b - CS_BLOCKS - CQ_BLOCKS - NSP_BLOCKS) * 256 + tid;
        int cp = i % (C / 2);
        int r  = (i / (C / 2)) % (NPAD - NQ);
        int t  = i / ((C / 2) * (NPAD - NQ));
        ((__half2*)Q)[((size_t)t * NPAD + NQ + r) * (C / 2) + cp] =
            __floats2half2_rn(0.f, 0.f);
    } else {
        // ---- zero colsum ----
        int i = (b - CS_BLOCKS - CQ_BLOCKS - NSP_BLOCKS - NQP_BLOCKS) * 256 + tid;
        if (i < CSZ_ELEMS)
            ((float4*)cs)[i] = make_float4(0.f, 0.f, 0.f, 0.f);
    }
}

// ---------------- kernel 2: fp16 HMMA GEMM (128x128) + fused column sum-of-squares ----------------
// R7/R10 config: 128 threads (4 warps 2x2), warp tile 64x64, 2 CTAs/SM, 3 stages.
__global__ void __launch_bounds__(128, 2) gemm_hmma_kernel(const __half* __restrict__ A,
                                                           const __half* __restrict__ B,
                                                           float* __restrict__ colsum) {
    extern __shared__ char smem[];
    const uint32_t sb = smem_u32(smem);

    const int tid  = threadIdx.x;
    const int warp = tid >> 5, lane = tid & 31;
    const int wm = warp & 1;          // 0..1 : 64-row half (M)
    const int wn = warp >> 1;         // 0..1 : 64-col half (N)
    const int gid = lane >> 2, tig = lane & 3;

    const int t  = blockIdx.z;
    const int m0 = blockIdx.y * BM;
    const int n0 = blockIdx.x * BN;
    const __half* Ap = A + ((size_t)t * MTOT + m0) * C;
    const __half* Bp = B + ((size_t)t * NPAD + n0) * C;

    const int arow = lane & 15;
    const int akof = (lane >> 4) * 16;
    const int brow = ((lane >> 4) << 3) | (lane & 7);
    const int bkof = ((lane >> 3) & 1) * 16;

    auto issue = [&](int kc) {
        const int s  = kc % STAGES;
        const int k0 = kc * BKH;
        const uint32_t sA = sb + s * STAGE_BYTES;
        const uint32_t sB = sA + A_BYTES;
        #pragma unroll
        for (int it = 0; it < 8; it++) {               // A: 1024 x 16B
            int i   = tid + it * 128;
            int row = i >> 3, ch = i & 7;
            uint32_t dst = sA + SWZ(row * 128 + ch * 16);
            const __half* src = Ap + (size_t)row * C + k0 + ch * 8;
            asm volatile("cp.async.cg.shared.global [%0], [%1], 16;" :: "r"(dst), "l"(src));
        }
        #pragma unroll
        for (int it = 0; it < 8; it++) {               // B: 1024 x 16B
            int i   = tid + it * 128;
            int row = i >> 3, ch = i & 7;
            uint32_t dst = sB + SWZ(row * 128 + ch * 16);
            const __half* src = Bp + (size_t)row * C + k0 + ch * 8;
            asm volatile("cp.async.cg.shared.global [%0], [%1], 16;" :: "r"(dst), "l"(src));
        }
        asm volatile("cp.async.commit_group;");
    };

    float acc[4][8][4];
    #pragma unroll
    for (int mi = 0; mi < 4; mi++)
        #pragma unroll
        for (int ni = 0; ni < 8; ni++)
            #pragma unroll
            for (int r = 0; r < 4; r++) acc[mi][ni][r] = 0.f;

    issue(0); issue(1);

    for (int kc = 0; kc < KT; kc++) {
        if (kc < KT - 1) { WAITG(1); }   // stage kc complete (1 newer group may pend)
        else             { WAITG(0); }
        __syncthreads();                 // data visible + all warps done reading stage (kc-1)%3
        if (kc + 2 < KT) issue(kc + 2);  // writes stage (kc-1)%3 — safe after the sync

        const uint32_t sA = sb + (kc % STAGES) * STAGE_BYTES;
        const uint32_t sB = sA + A_BYTES;

        #pragma unroll
        for (int ks = 0; ks < 4; ks++) {
            const int kb = ks * 32;
            uint32_t a[4][4], b[8][2];
            #pragma unroll
            for (int mi = 0; mi < 4; mi++) {
                uint32_t addr = sA + SWZ((wm * 64 + mi * 16 + arow) * 128 + kb + akof);
                asm volatile("ldmatrix.sync.aligned.m8n8.x4.shared.b16 {%0,%1,%2,%3}, [%4];"
                             : "=r"(a[mi][0]), "=r"(a[mi][1]), "=r"(a[mi][2]), "=r"(a[mi][3])
                             : "r"(addr));
            }
            #pragma unroll
            for (int nj = 0; nj < 4; nj++) {
                uint32_t addr = sB + SWZ((wn * 64 + nj * 16 + brow) * 128 + kb + bkof);
                asm volatile("ldmatrix.sync.aligned.m8n8.x4.shared.b16 {%0,%1,%2,%3}, [%4];"
                             : "=r"(b[nj*2][0]), "=r"(b[nj*2][1]),
                               "=r"(b[nj*2+1][0]), "=r"(b[nj*2+1][1])
                             : "r"(addr));
            }
            #pragma unroll
            for (int mi = 0; mi < 4; mi++)
                #pragma unroll
                for (int ni = 0; ni < 8; ni++) {
                    asm volatile(
                        "mma.sync.aligned.m16n8k16.row.col.f32.f16.f16.f32 "
                        "{%0,%1,%2,%3}, {%4,%5,%6,%7}, {%8,%9}, {%0,%1,%2,%3};"
                        : "+f"(acc[mi][ni][0]), "+f"(acc[mi][ni][1]),
                          "+f"(acc[mi][ni][2]), "+f"(acc[mi][ni][3])
                        : "r"(a[mi][0]), "r"(a[mi][1]), "r"(a[mi][2]), "r"(a[mi][3]),
                          "r"(b[ni][0]), "r"(b[ni][1]));
                }
        }
    }

    // -------- fused epilogue: column sum of squares over this CTA's 128 rows --------
    const int way = m0 / MS;
    float* cs = colsum + ((size_t)t * WAY + way) * NPAD + n0;
    #pragma unroll
    for (int ni = 0; ni < 8; ni++) {
        float v0 = 0.f, v1 = 0.f;
        #pragma unroll
        for (int mi = 0; mi < 4; mi++) {
            v0 += acc[mi][ni][0] * acc[mi][ni][0] + acc[mi][ni][2] * acc[mi][ni][2];
            v1 += acc[mi][ni][1] * acc[mi][ni][1] + acc[mi][ni][3] * acc[mi][ni][3];
        }
        #pragma unroll
        for (int o = 4; o < 32; o <<= 1) {
            v0 += __shfl_xor_sync(~0u, v0, o);
            v1 += __shfl_xor_sync(~0u, v1, o);
        }
        if (gid == 0) {
            int col = wn * 64 + ni * 8 + tig * 2;
            atomicAdd(&cs[col], v0);
            atomicAdd(&cs[col + 1], v1);
        }
    }
}

// ---------------- kernel 3: /99, LeakyReLU(0.2), conv1d(k=stride=100), +bias ----------------
__global__ void final_kernel(const float* __restrict__ colsum, const float* __restrict__ cw,
                             const float* __restrict__ cb, float* __restrict__ out) {
    int wid  = (blockIdx.x * blockDim.x + threadIdx.x) >> 5;
    int lane = threadIdx.x & 31;
    if (wid >= T * WQ * WAY) return;
    int w = wid % WAY;
    int q = (wid / WAY) % WQ;
    int t = wid / (WAY * WQ);
    const float* cs = colsum + ((size_t)t * WAY + w) * NPAD + q * HW;
    float v = 0.f;
    #pragma unroll
    for (int i = 0; i < 4; i++) {
        int n = lane + 32 * i;
        if (n < HW) {
            float x = cs[n] * (1.0f / 99.0f);
            x = (x >= 0.f) ? x : 0.2f * x;
            v += x * cw[n];
        }
    }
    #pragma unroll
    for (int o = 16; o; o >>= 1) v += __shfl_xor_sync(~0u, v, o);
    if (!lane) out[wid] = v + cb[0];
}

// ---------------- launch (3 kernels) ----------------
extern "C" void kernel_launch(void* const* d_in, const int* in_sizes, int n_in,
                              void* d_out, int out_size) {
    const float* qf = (const float*)d_in[0];
    const float* sf = (const float*)d_in[1];
    const float* cw = (const float*)d_in[2];
    const float* cb = (const float*)d_in[3];
    float* out = (float*)d_out;

    __half *dS, *dQ;
    float *dCS;
    cudaGetSymbolAddress((void**)&dS,  g_S16);
    cudaGetSymbolAddress((void**)&dQ,  g_Q16);
    cudaGetSymbolAddress((void**)&dCS, g_colsum);

    // 1) unified prep: support(two-pass) + query + pads + zero colsum
    prep_kernel<<<MERGED_BLOCKS, 256>>>(sf, qf, dS, dQ, dCS);
    // 2) GEMM + fused sum-of-squares
    cudaFuncSetAttribute(gemm_hmma_kernel, cudaFuncAttributeMaxDynamicSharedMemorySize, SMEM_TOTAL);
    dim3 grid(NPAD / BN, MTOT / BM, T);   // (59, 20, 4)
    gemm_hmma_kernel<<<grid, 128, SMEM_TOTAL>>>(dS, dQ, dCS);
    // 3) final score
    int warps = T * WQ * WAY;
    final_kernel<<<(warps * 32 + 255) / 256, 256>>>(dCS, cw, cb, out);
}